// round 16
// baseline (speedup 1.0000x reference)
#include <cuda_runtime.h>
#include <cstdint>

#define TPB 128
typedef unsigned long long u64;
typedef unsigned int u32;

// ---- Blackwell packed f32x2 FMA (ptxas never auto-fuses this) ----
__device__ __forceinline__ u64 ffma2(u64 a, u64 b, u64 c) {
    u64 d;
    asm("fma.rn.f32x2 %0, %1, %2, %3;" : "=l"(d) : "l"(a), "l"(b), "l"(c));
    return d;
}
__device__ __forceinline__ u64 pack2(float lo, float hi) {
    u64 d;
    u32 a = __float_as_uint(lo), b = __float_as_uint(hi);
    asm("mov.b64 %0, {%1,%2};" : "=l"(d) : "r"(a), "r"(b));
    return d;
}
__device__ __forceinline__ u64 dup2(float v) {
    u64 d;
    u32 a = __float_as_uint(v);
    asm("mov.b64 %0, {%1,%1};" : "=l"(d) : "r"(a));
    return d;
}
__device__ __forceinline__ void unpack2(u64 d, float& lo, float& hi) {
    u32 a, b;
    asm("mov.b64 {%0,%1}, %2;" : "=r"(a), "=r"(b) : "l"(d));
    lo = __uint_as_float(a);
    hi = __uint_as_float(b);
}
// f32 pair -> f16x2 (lo in low half)
__device__ __forceinline__ u32 cvt2h(float lo, float hi) {
    u32 d;
    asm("cvt.rn.f16x2.f32 %0, %1, %2;" : "=r"(d) : "f"(hi), "f"(lo));
    return d;
}
// dual tanh on one MUFU instruction (halves MUFU pressure)
__device__ __forceinline__ u32 tanh2(u32 a) {
    u32 d;
    asm("tanh.approx.f16x2 %0, %1;" : "=r"(d) : "r"(a));
    return d;
}
__device__ __forceinline__ void h2f(u32 a, float& lo, float& hi) {
    asm("{.reg .f16 l, h;\n\t mov.b32 {l, h}, %2;\n\t"
        "cvt.f32.f16 %0, l;\n\t cvt.f32.f16 %1, h;}"
        : "=f"(lo), "=f"(hi) : "r"(a));
}
template<int OFF>
__device__ __forceinline__ float lds32(unsigned a) {
    float v;
    asm volatile("ld.shared.f32 %0, [%1+%2];" : "=f"(v) : "r"(a), "n"(OFF));
    return v;
}
__device__ __forceinline__ void cp16(unsigned dst, const void* src) {
    asm volatile("cp.async.cg.shared.global [%0], [%1], 16;"
                 :: "r"(dst), "l"(src) : "memory");
}
__device__ __forceinline__ void cp_commit() {
    asm volatile("cp.async.commit_group;" ::: "memory");
}
__device__ __forceinline__ void cp_wait_all() {
    asm volatile("cp.async.wait_group 0;" ::: "memory");
}

// One row (neuron n, 8 features): 8 scalar broadcast z loads, register dup,
// 32 packed W1 FMAs (4 chains), 4x dual-f16 tanh, scalar W2 dot (2 chains).
template<int RO>
__device__ __forceinline__ float row_compute(unsigned za,
                                             const u64 (&w1p)[8][4],
                                             const u64 (&b1p)[4],
                                             const float (&w2s)[8],
                                             float ybias)
{
    float f0 = lds32<RO +  0>(za);
    float f1 = lds32<RO +  4>(za);
    float f2 = lds32<RO +  8>(za);
    float f3 = lds32<RO + 12>(za);
    float f4 = lds32<RO + 16>(za);
    float f5 = lds32<RO + 20>(za);
    float f6 = lds32<RO + 24>(za);
    float f7 = lds32<RO + 28>(za);

    u64 z0 = dup2(f0), z1 = dup2(f1), z2 = dup2(f2), z3 = dup2(f3);
    u64 z4 = dup2(f4), z5 = dup2(f5), z6 = dup2(f6), z7 = dup2(f7);

    u64 a0 = ffma2(z0, w1p[0][0], b1p[0]);
    u64 a1 = ffma2(z0, w1p[0][1], b1p[1]);
    u64 a2 = ffma2(z0, w1p[0][2], b1p[2]);
    u64 a3 = ffma2(z0, w1p[0][3], b1p[3]);
    a0 = ffma2(z1, w1p[1][0], a0); a1 = ffma2(z1, w1p[1][1], a1);
    a2 = ffma2(z1, w1p[1][2], a2); a3 = ffma2(z1, w1p[1][3], a3);
    a0 = ffma2(z2, w1p[2][0], a0); a1 = ffma2(z2, w1p[2][1], a1);
    a2 = ffma2(z2, w1p[2][2], a2); a3 = ffma2(z2, w1p[2][3], a3);
    a0 = ffma2(z3, w1p[3][0], a0); a1 = ffma2(z3, w1p[3][1], a1);
    a2 = ffma2(z3, w1p[3][2], a2); a3 = ffma2(z3, w1p[3][3], a3);
    a0 = ffma2(z4, w1p[4][0], a0); a1 = ffma2(z4, w1p[4][1], a1);
    a2 = ffma2(z4, w1p[4][2], a2); a3 = ffma2(z4, w1p[4][3], a3);
    a0 = ffma2(z5, w1p[5][0], a0); a1 = ffma2(z5, w1p[5][1], a1);
    a2 = ffma2(z5, w1p[5][2], a2); a3 = ffma2(z5, w1p[5][3], a3);
    a0 = ffma2(z6, w1p[6][0], a0); a1 = ffma2(z6, w1p[6][1], a1);
    a2 = ffma2(z6, w1p[6][2], a2); a3 = ffma2(z6, w1p[6][3], a3);
    a0 = ffma2(z7, w1p[7][0], a0); a1 = ffma2(z7, w1p[7][1], a1);
    a2 = ffma2(z7, w1p[7][2], a2); a3 = ffma2(z7, w1p[7][3], a3);

    // epilogue: f16x2 tanh (4 MUFU instead of 8) + scalar W2 dot
    float h0, h1;
    unpack2(a0, h0, h1);
    u32 c0 = tanh2(cvt2h(h0, h1));
    unpack2(a1, h0, h1);
    u32 c1 = tanh2(cvt2h(h0, h1));
    unpack2(a2, h0, h1);
    u32 c2 = tanh2(cvt2h(h0, h1));
    unpack2(a3, h0, h1);
    u32 c3 = tanh2(cvt2h(h0, h1));

    float t0, t1;
    h2f(c0, t0, t1);
    float ya = fmaf(t0, w2s[0], ybias);
    float yb = t1 * w2s[1];
    h2f(c1, t0, t1);
    ya = fmaf(t0, w2s[2], ya);
    yb = fmaf(t1, w2s[3], yb);
    h2f(c2, t0, t1);
    ya = fmaf(t0, w2s[4], ya);
    yb = fmaf(t1, w2s[5], yb);
    h2f(c3, t0, t1);
    ya = fmaf(t0, w2s[6], ya);
    yb = fmaf(t1, w2s[7], yb);
    return ya + yb;
}

__global__ void __launch_bounds__(TPB, 4)
fans_kernel(const float* __restrict__ x,
            const float* __restrict__ W1,
            const float* __restrict__ b1,
            const float* __restrict__ W2,
            const float* __restrict__ b2,
            float* __restrict__ out,
            int ntiles)
{
    // RAW x tile: 32 rows x 40 cols fp32 (slots 32..39 mirror cols 0..7 so
    // every neuron's window cols n..n+7 is contiguous). Double-buffered.
    __shared__ __align__(16) float xs[2][32][40];   // 10 KB

    const int tid  = threadIdx.x;
    const int lane = tid & 31;
    const int warp = tid >> 5;
    const int nl   = lane & 7;
    const int fg   = lane >> 3;       // 0..3, feature group of 8
    const int n    = warp * 8 + nl;   // neuron 0..31

    // ---- register-resident weight slice (loaded once) ----
    // window position t reads col (n+t)%32; sorted (np.nonzero) order maps
    // that to k = (t + wrap) % 8, wrap = max(0, n+8-32): pre-rotate W1.
    const int wrapc = (n + 8 > 32) ? (n + 8 - 32) : 0;
    u64 w1p[8][4];
    #pragma unroll
    for (int t = 0; t < 8; t++) {
        int k = t + wrapc;
        if (k >= 8) k -= 8;
        const float* wp = W1 + n * 256 + k * 32 + fg * 8;
        ulonglong2 a = *(const ulonglong2*)wp;
        ulonglong2 b = *(const ulonglong2*)(wp + 4);
        w1p[t][0] = a.x; w1p[t][1] = a.y; w1p[t][2] = b.x; w1p[t][3] = b.y;
    }
    u64 b1p[4];
    {
        const float* bp = b1 + n * 32 + fg * 8;
        ulonglong2 a = *(const ulonglong2*)bp;
        ulonglong2 b = *(const ulonglong2*)(bp + 4);
        b1p[0] = a.x; b1p[1] = a.y; b1p[2] = b.x; b1p[3] = b.y;
    }
    float w2s[8];
    #pragma unroll
    for (int j = 0; j < 8; j++) w2s[j] = W2[n * 32 + fg * 8 + j];
    const float ybias = (fg == 0) ? b2[n] : 0.0f;
    const bool fb0 = (fg & 1) != 0;
    const bool fb1 = (fg & 2) != 0;

    unsigned sbase;
    asm("{ .reg .u64 t; cvta.to.shared.u64 t, %1; cvt.u32.u64 %0, t; }"
        : "=r"(sbase) : "l"(&xs[0][0][0]));
    const unsigned zb = sbase + (unsigned)(n * 4);   // window base = col n

    int tile = blockIdx.x;
    if (tile >= ntiles) return;
    const char* gxb = (const char*)x;

    // staging map (cp.async, 16B granules):
    //   main: thread covers float4 chunks m0=2*tid, m0+1 of the 32x32 tile
    //   wrap: threads 0..63 copy cols 0..7 of each row into slots 32..39
    const int m0 = tid * 2;
    const unsigned d0 = (unsigned)((m0 >> 3) * 160 + (m0 & 7) * 16);
    const unsigned d1 = (unsigned)(((m0 + 1) >> 3) * 160 + ((m0 + 1) & 7) * 16);
    const unsigned dw = (unsigned)((tid >> 1) * 160 + 128 + (tid & 1) * 16);
    const unsigned g0 = (unsigned)(m0 * 16);
    const unsigned g1 = (unsigned)((m0 + 1) * 16);
    const unsigned gw = (unsigned)((tid >> 1) * 128 + (tid & 1) * 16);

    // ---- stage first tile ----
    {
        const char* src = gxb + (size_t)tile * 4096;
        cp16(sbase + d0, src + g0);
        cp16(sbase + d1, src + g1);
        if (tid < 64) cp16(sbase + dw, src + gw);
        cp_commit();
    }
    cp_wait_all();
    __syncthreads();

    int buf = 0;
    for (;;) {
        const int next = tile + gridDim.x;
        const bool have_next = next < ntiles;
        if (have_next) {
            const unsigned sb = sbase + (unsigned)((buf ^ 1) * 5120);
            const char* src = gxb + (size_t)next * 4096;
            cp16(sb + d0, src + g0);
            cp16(sb + d1, src + g1);
            if (tid < 64) cp16(sb + dw, src + gw);
            cp_commit();
        }

        // ---- compute 32 rows of the current tile ----
        float* outb = out + (size_t)tile * 1024 + fg * 32 + n;
        unsigned za = zb + (unsigned)(buf * 5120);

        #pragma unroll 4
        for (int g = 0; g < 8; g++) {
            // 4 fully independent rows: wide scheduling window for ptxas
            float y0 = row_compute<0>  (za, w1p, b1p, w2s, ybias);
            float y1 = row_compute<160>(za, w1p, b1p, w2s, ybias);
            float y2 = row_compute<320>(za, w1p, b1p, w2s, ybias);
            float y3 = row_compute<480>(za, w1p, b1p, w2s, ybias);

            // transpose-reduce over fg (lane bits 3,4): lane fg ends with
            // the COMPLETE y of row (4g + fg); single unpredicated store.
            float s1 = __shfl_xor_sync(0xffffffffu, fb0 ? y0 : y1, 8);
            float pA = (fb0 ? y1 : y0) + s1;
            float s2 = __shfl_xor_sync(0xffffffffu, fb0 ? y2 : y3, 8);
            float qA = (fb0 ? y3 : y2) + s2;
            float s3 = __shfl_xor_sync(0xffffffffu, fb1 ? pA : qA, 16);
            outb[0] = (fb1 ? qA : pA) + s3;

            outb += 128;
            za += 640;
        }

        if (!have_next) break;
        cp_wait_all();
        __syncthreads();
        buf ^= 1;
        tile = next;
    }
}

extern "C" void kernel_launch(void* const* d_in, const int* in_sizes, int n_in,
                              void* d_out, int out_size) {
    const float* x  = (const float*)d_in[0];
    const float* W1 = (const float*)d_in[1];
    const float* b1 = (const float*)d_in[2];
    const float* W2 = (const float*)d_in[3];
    const float* b2 = (const float*)d_in[4];
    // d_in[5] (idx) unused: circular window + np.nonzero sort order are
    // reproduced analytically (W1 k-rotation at register-load time).
    float* out = (float*)d_out;

    const int B = in_sizes[0] / 32;
    const int ntiles = B / 32;
    int grid = 148 * 4;                  // persistent, 4 blocks/SM
    if (grid > ntiles) grid = ntiles;
    fans_kernel<<<grid, TPB>>>(x, W1, b1, W2, b2, out, ntiles);
}

// round 17
// speedup vs baseline: 1.0593x; 1.0593x over previous
#include <cuda_runtime.h>
#include <cstdint>

#define TPB 128
typedef unsigned long long u64;
typedef unsigned int u32;

// ---- Blackwell packed f32x2 FMA (ptxas never auto-fuses this) ----
__device__ __forceinline__ u64 ffma2(u64 a, u64 b, u64 c) {
    u64 d;
    asm("fma.rn.f32x2 %0, %1, %2, %3;" : "=l"(d) : "l"(a), "l"(b), "l"(c));
    return d;
}
__device__ __forceinline__ u64 pack2(float lo, float hi) {
    u64 d;
    u32 a = __float_as_uint(lo), b = __float_as_uint(hi);
    asm("mov.b64 %0, {%1,%2};" : "=l"(d) : "r"(a), "r"(b));
    return d;
}
__device__ __forceinline__ u64 dup2(float v) {
    u64 d;
    u32 a = __float_as_uint(v);
    asm("mov.b64 %0, {%1,%1};" : "=l"(d) : "r"(a));
    return d;
}
__device__ __forceinline__ void unpack2(u64 d, float& lo, float& hi) {
    u32 a, b;
    asm("mov.b64 {%0,%1}, %2;" : "=r"(a), "=r"(b) : "l"(d));
    lo = __uint_as_float(a);
    hi = __uint_as_float(b);
}
// f32 pair -> f16x2 (lo goes to low half)
__device__ __forceinline__ u32 cvt2h(float lo, float hi) {
    u32 d;
    asm("cvt.rn.f16x2.f32 %0, %1, %2;" : "=r"(d) : "f"(hi), "f"(lo));
    return d;
}
// dual tanh on one MUFU instruction (halves MUFU pressure)
__device__ __forceinline__ u32 tanh2(u32 a) {
    u32 d;
    asm("tanh.approx.f16x2 %0, %1;" : "=r"(d) : "r"(a));
    return d;
}
// packed half2 FMA (W2 dot stays in f16 -> no per-feature cvt tax)
__device__ __forceinline__ u32 hfma2(u32 a, u32 b, u32 c) {
    u32 d;
    asm("fma.rn.f16x2 %0, %1, %2, %3;" : "=r"(d) : "r"(a), "r"(b), "r"(c));
    return d;
}
__device__ __forceinline__ void h2f(u32 a, float& lo, float& hi) {
    asm("{.reg .f16 l, h;\n\t mov.b32 {l, h}, %2;\n\t"
        "cvt.f32.f16 %0, l;\n\t cvt.f32.f16 %1, h;}"
        : "=f"(lo), "=f"(hi) : "r"(a));
}
template<int OFF>
__device__ __forceinline__ float lds32(unsigned a) {
    float v;
    asm volatile("ld.shared.f32 %0, [%1+%2];" : "=f"(v) : "r"(a), "n"(OFF));
    return v;
}
__device__ __forceinline__ void cp16(unsigned dst, const void* src) {
    asm volatile("cp.async.cg.shared.global [%0], [%1], 16;"
                 :: "r"(dst), "l"(src) : "memory");
}
__device__ __forceinline__ void cp_commit() {
    asm volatile("cp.async.commit_group;" ::: "memory");
}
__device__ __forceinline__ void cp_wait_all() {
    asm volatile("cp.async.wait_group 0;" ::: "memory");
}

// One row (neuron n, 8 features): 8 scalar broadcast z loads, register dup,
// 32 packed f32x2 W1 FMAs (4 chains), then f16 epilogue: 4 dual-tanh MUFUs
// + 4 HFMA2 (two 2-deep f16 chains) + 2 final f32 conversions.
template<int RO>
__device__ __forceinline__ float row_compute(unsigned za,
                                             const u64 (&w1p)[8][4],
                                             const u64 (&b1p)[4],
                                             const u32 (&w2h)[4],
                                             float ybias)
{
    float f0 = lds32<RO +  0>(za);
    float f1 = lds32<RO +  4>(za);
    float f2 = lds32<RO +  8>(za);
    float f3 = lds32<RO + 12>(za);
    float f4 = lds32<RO + 16>(za);
    float f5 = lds32<RO + 20>(za);
    float f6 = lds32<RO + 24>(za);
    float f7 = lds32<RO + 28>(za);

    u64 z0 = dup2(f0), z1 = dup2(f1), z2 = dup2(f2), z3 = dup2(f3);
    u64 z4 = dup2(f4), z5 = dup2(f5), z6 = dup2(f6), z7 = dup2(f7);

    u64 a0 = ffma2(z0, w1p[0][0], b1p[0]);
    u64 a1 = ffma2(z0, w1p[0][1], b1p[1]);
    u64 a2 = ffma2(z0, w1p[0][2], b1p[2]);
    u64 a3 = ffma2(z0, w1p[0][3], b1p[3]);
    a0 = ffma2(z1, w1p[1][0], a0); a1 = ffma2(z1, w1p[1][1], a1);
    a2 = ffma2(z1, w1p[1][2], a2); a3 = ffma2(z1, w1p[1][3], a3);
    a0 = ffma2(z2, w1p[2][0], a0); a1 = ffma2(z2, w1p[2][1], a1);
    a2 = ffma2(z2, w1p[2][2], a2); a3 = ffma2(z2, w1p[2][3], a3);
    a0 = ffma2(z3, w1p[3][0], a0); a1 = ffma2(z3, w1p[3][1], a1);
    a2 = ffma2(z3, w1p[3][2], a2); a3 = ffma2(z3, w1p[3][3], a3);
    a0 = ffma2(z4, w1p[4][0], a0); a1 = ffma2(z4, w1p[4][1], a1);
    a2 = ffma2(z4, w1p[4][2], a2); a3 = ffma2(z4, w1p[4][3], a3);
    a0 = ffma2(z5, w1p[5][0], a0); a1 = ffma2(z5, w1p[5][1], a1);
    a2 = ffma2(z5, w1p[5][2], a2); a3 = ffma2(z5, w1p[5][3], a3);
    a0 = ffma2(z6, w1p[6][0], a0); a1 = ffma2(z6, w1p[6][1], a1);
    a2 = ffma2(z6, w1p[6][2], a2); a3 = ffma2(z6, w1p[6][3], a3);
    a0 = ffma2(z7, w1p[7][0], a0); a1 = ffma2(z7, w1p[7][1], a1);
    a2 = ffma2(z7, w1p[7][2], a2); a3 = ffma2(z7, w1p[7][3], a3);

    // f16 epilogue: convert acc pairs once, dual tanh, W2 dot in f16x2
    float h0, h1;
    unpack2(a0, h0, h1);
    u32 c0 = tanh2(cvt2h(h0, h1));
    unpack2(a1, h0, h1);
    u32 c1 = tanh2(cvt2h(h0, h1));
    unpack2(a2, h0, h1);
    u32 c2 = tanh2(cvt2h(h0, h1));
    unpack2(a3, h0, h1);
    u32 c3 = tanh2(cvt2h(h0, h1));

    u32 accA = hfma2(c0, w2h[0], 0u);        // +0.0h pair
    accA = hfma2(c1, w2h[1], accA);          // 2-deep f16 chain
    u32 accB = hfma2(c2, w2h[2], 0u);
    accB = hfma2(c3, w2h[3], accB);

    float pa, pb, qa, qb;
    h2f(accA, pa, pb);
    h2f(accB, qa, qb);
    return (pa + pb) + (qa + qb) + ybias;    // b2 applied in f32
}

__global__ void __launch_bounds__(TPB, 4)
fans_kernel(const float* __restrict__ x,
            const float* __restrict__ W1,
            const float* __restrict__ b1,
            const float* __restrict__ W2,
            const float* __restrict__ b2,
            float* __restrict__ out,
            int ntiles)
{
    // RAW x tile: 32 rows x 40 cols fp32 (slots 32..39 mirror cols 0..7 so
    // every neuron's window cols n..n+7 is contiguous). Double-buffered.
    __shared__ __align__(16) float xs[2][32][40];   // 10 KB

    const int tid  = threadIdx.x;
    const int lane = tid & 31;
    const int warp = tid >> 5;
    const int nl   = lane & 7;
    const int fg   = lane >> 3;       // 0..3, feature group of 8
    const int n    = warp * 8 + nl;   // neuron 0..31

    // ---- register-resident weight slice (loaded once) ----
    // window position t reads col (n+t)%32; sorted (np.nonzero) order maps
    // that to k = (t + wrap) % 8, wrap = max(0, n+8-32): pre-rotate W1.
    const int wrapc = (n + 8 > 32) ? (n + 8 - 32) : 0;
    u64 w1p[8][4];
    #pragma unroll
    for (int t = 0; t < 8; t++) {
        int k = t + wrapc;
        if (k >= 8) k -= 8;
        const float* wp = W1 + n * 256 + k * 32 + fg * 8;
        ulonglong2 a = *(const ulonglong2*)wp;
        ulonglong2 b = *(const ulonglong2*)(wp + 4);
        w1p[t][0] = a.x; w1p[t][1] = a.y; w1p[t][2] = b.x; w1p[t][3] = b.y;
    }
    u64 b1p[4];
    {
        const float* bp = b1 + n * 32 + fg * 8;
        ulonglong2 a = *(const ulonglong2*)bp;
        ulonglong2 b = *(const ulonglong2*)(bp + 4);
        b1p[0] = a.x; b1p[1] = a.y; b1p[2] = b.x; b1p[3] = b.y;
    }
    u32 w2h[4];
    #pragma unroll
    for (int j = 0; j < 4; j++) {
        float wlo = W2[n * 32 + fg * 8 + 2 * j];
        float whi = W2[n * 32 + fg * 8 + 2 * j + 1];
        w2h[j] = cvt2h(wlo, whi);
    }
    const float ybias = (fg == 0) ? b2[n] : 0.0f;
    const bool fb0 = (fg & 1) != 0;
    const bool fb1 = (fg & 2) != 0;

    unsigned sbase;
    asm("{ .reg .u64 t; cvta.to.shared.u64 t, %1; cvt.u32.u64 %0, t; }"
        : "=r"(sbase) : "l"(&xs[0][0][0]));
    const unsigned zb = sbase + (unsigned)(n * 4);   // window base = col n

    int tile = blockIdx.x;
    if (tile >= ntiles) return;
    const char* gxb = (const char*)x;

    // staging map (cp.async, 16B granules):
    //   main: thread covers float4 chunks m0=2*tid, m0+1 of the 32x32 tile
    //   wrap: threads 0..63 copy cols 0..7 of each row into slots 32..39
    const int m0 = tid * 2;
    const unsigned d0 = (unsigned)((m0 >> 3) * 160 + (m0 & 7) * 16);
    const unsigned d1 = (unsigned)(((m0 + 1) >> 3) * 160 + ((m0 + 1) & 7) * 16);
    const unsigned dw = (unsigned)((tid >> 1) * 160 + 128 + (tid & 1) * 16);
    const unsigned g0 = (unsigned)(m0 * 16);
    const unsigned g1 = (unsigned)((m0 + 1) * 16);
    const unsigned gw = (unsigned)((tid >> 1) * 128 + (tid & 1) * 16);

    // ---- stage first tile ----
    {
        const char* src = gxb + (size_t)tile * 4096;
        cp16(sbase + d0, src + g0);
        cp16(sbase + d1, src + g1);
        if (tid < 64) cp16(sbase + dw, src + gw);
        cp_commit();
    }
    cp_wait_all();
    __syncthreads();

    int buf = 0;
    for (;;) {
        const int next = tile + gridDim.x;
        const bool have_next = next < ntiles;
        if (have_next) {
            const unsigned sb = sbase + (unsigned)((buf ^ 1) * 5120);
            const char* src = gxb + (size_t)next * 4096;
            cp16(sb + d0, src + g0);
            cp16(sb + d1, src + g1);
            if (tid < 64) cp16(sb + dw, src + gw);
            cp_commit();
        }

        // ---- compute 32 rows of the current tile ----
        float* outb = out + (size_t)tile * 1024 + fg * 32 + n;
        unsigned za = zb + (unsigned)(buf * 5120);

        #pragma unroll 4
        for (int g = 0; g < 8; g++) {
            // 4 fully independent rows: wide scheduling window for ptxas
            float y0 = row_compute<0>  (za, w1p, b1p, w2h, ybias);
            float y1 = row_compute<160>(za, w1p, b1p, w2h, ybias);
            float y2 = row_compute<320>(za, w1p, b1p, w2h, ybias);
            float y3 = row_compute<480>(za, w1p, b1p, w2h, ybias);

            // transpose-reduce over fg (lane bits 3,4): lane fg ends with
            // the COMPLETE y of row (4g + fg); single unpredicated store.
            float s1 = __shfl_xor_sync(0xffffffffu, fb0 ? y0 : y1, 8);
            float pA = (fb0 ? y1 : y0) + s1;
            float s2 = __shfl_xor_sync(0xffffffffu, fb0 ? y2 : y3, 8);
            float qA = (fb0 ? y3 : y2) + s2;
            float s3 = __shfl_xor_sync(0xffffffffu, fb1 ? pA : qA, 16);
            outb[0] = (fb1 ? qA : pA) + s3;

            outb += 128;
            za += 640;
        }

        if (!have_next) break;
        cp_wait_all();
        __syncthreads();
        buf ^= 1;
        tile = next;
    }
}

extern "C" void kernel_launch(void* const* d_in, const int* in_sizes, int n_in,
                              void* d_out, int out_size) {
    const float* x  = (const float*)d_in[0];
    const float* W1 = (const float*)d_in[1];
    const float* b1 = (const float*)d_in[2];
    const float* W2 = (const float*)d_in[3];
    const float* b2 = (const float*)d_in[4];
    // d_in[5] (idx) unused: circular window + np.nonzero sort order are
    // reproduced analytically (W1 k-rotation at register-load time).
    float* out = (float*)d_out;

    const int B = in_sizes[0] / 32;
    const int ntiles = B / 32;
    int grid = 148 * 4;                  // persistent, 4 blocks/SM
    if (grid > ntiles) grid = ntiles;
    fans_kernel<<<grid, TPB>>>(x, W1, b1, W2, b2, out, ntiles);
}